// round 2
// baseline (speedup 1.0000x reference)
#include <cuda_runtime.h>
#include <math.h>

#define Bz 2
#define Sq 2048
#define Dm 1024
#define Hn 16
#define DH 64
#define NREL 129
#define BHN (Bz*Hn)

// scratch for projected Q,K,V in head-split layout [(b*H+h), s, d]
__device__ float g_Q[BHN * Sq * DH];
__device__ float g_K[BHN * Sq * DH];
__device__ float g_V[BHN * Sq * DH];

// ---------------------------------------------------------------------------
// Kernel 1: fused QKV projection GEMM
// Y = X @ W + bias   (X:[4096,1024], W:[1024,1024]), head-split store.
// grid (N/64=16, M/64=64, 3), block 256, 64x64x16 tiles, 4x4 per thread.
// ---------------------------------------------------------------------------
__global__ void qkv_proj_kernel(const float* __restrict__ Xq,
                                const float* __restrict__ Xk,
                                const float* __restrict__ Xv,
                                const float* __restrict__ Wq,
                                const float* __restrict__ Wk,
                                const float* __restrict__ Wv,
                                const float* __restrict__ bq,
                                const float* __restrict__ bk,
                                const float* __restrict__ bv)
{
    const float* X; const float* W; const float* bias; float* out;
    if (blockIdx.z == 0)      { X = Xq; W = Wq; bias = bq; out = g_Q; }
    else if (blockIdx.z == 1) { X = Xk; W = Wk; bias = bk; out = g_K; }
    else                      { X = Xv; W = Wv; bias = bv; out = g_V; }

    __shared__ float Xs[64][16];     // [m][kk] — conflict-free store & broadcast read
    __shared__ float Ws[16][65];     // [kk][n] padded

    const int tid = threadIdx.x;
    const int tx = tid & 15;         // 0..15 -> 4 n-cols each
    const int ty = tid >> 4;         // 0..15 -> 4 m-rows each
    const int m0 = blockIdx.y * 64;
    const int n0 = blockIdx.x * 64;

    float acc[4][4] = {};

    for (int k0 = 0; k0 < Dm; k0 += 16) {
        // load X tile: 64 rows x 16 k
        {
            const int kk = tid & 15;
            const int mb = tid >> 4;
            #pragma unroll
            for (int r = 0; r < 4; r++) {
                int m = mb + r * 16;
                Xs[m][kk] = X[(size_t)(m0 + m) * Dm + k0 + kk];
            }
        }
        // load W tile: 16 k x 64 n
        {
            const int n  = tid & 63;
            const int kb = tid >> 6;
            #pragma unroll
            for (int r = 0; r < 4; r++) {
                int kk = kb + r * 4;
                Ws[kk][n] = W[(size_t)(k0 + kk) * Dm + n0 + n];
            }
        }
        __syncthreads();

        #pragma unroll
        for (int kk = 0; kk < 16; kk++) {
            float a[4], bb[4];
            #pragma unroll
            for (int i = 0; i < 4; i++) a[i]  = Xs[ty * 4 + i][kk];
            #pragma unroll
            for (int j = 0; j < 4; j++) bb[j] = Ws[kk][tx * 4 + j];
            #pragma unroll
            for (int i = 0; i < 4; i++)
                #pragma unroll
                for (int j = 0; j < 4; j++)
                    acc[i][j] += a[i] * bb[j];
        }
        __syncthreads();
    }

    // head-split store: out[((b*H+h)*S + s)*DH + d]
    #pragma unroll
    for (int i = 0; i < 4; i++) {
        const int m = m0 + ty * 4 + i;
        const int b = m >> 11;          // / 2048
        const int s = m & 2047;
        #pragma unroll
        for (int j = 0; j < 4; j++) {
            const int n = n0 + tx * 4 + j;
            const int h = n >> 6;
            const int d = n & 63;
            out[(((size_t)(b * Hn + h) * Sq + s) * DH) + d] = acc[i][j] + bias[n];
        }
    }
}

// ---------------------------------------------------------------------------
// Kernel 2: flash attention with relative-position key bias.
// grid (S/64=32, B*H=32), block 256. 64 q-rows per CTA, k tiles of 64.
// bias collapsed to a per-row 129-entry lookup: pb[r][t] = q_r . rel_table[t]
// ---------------------------------------------------------------------------
#define LDP 65      // padded row stride for 64-wide tiles
#define PBL 132     // padded row stride for the 129-entry bias table

extern __shared__ float smem[];

__global__ void attn_kernel(const float* __restrict__ mask,
                            const float* __restrict__ rel_table,
                            float* __restrict__ out)
{
    float* Qs = smem;                    // 64*65
    float* Ks = Qs + 64 * LDP;           // 64*65
    float* Vs = Ks + 64 * LDP;           // 64*65
    float* Ps = Vs + 64 * LDP;           // 64*65
    float* pb = Ps + 64 * LDP;           // 64*132

    const int tid = threadIdx.x;
    const int tx = tid & 15;             // 4 k-cols / d-cols each
    const int ty = tid >> 4;             // 4 q-rows each
    const int bh = blockIdx.y;
    const int b  = bh / Hn;
    const int h  = bh - b * Hn;
    const int q0 = blockIdx.x * 64;

    const float* Qg = g_Q + (size_t)bh * Sq * DH;
    const float* Kg = g_K + (size_t)bh * Sq * DH;
    const float* Vg = g_V + (size_t)bh * Sq * DH;
    const float* maskb = mask + (size_t)b * Sq;

    // load Q tile
    for (int idx = tid; idx < 64 * 64; idx += 256) {
        int r = idx >> 6, d = idx & 63;
        Qs[r * LDP + d] = Qg[(size_t)(q0 + r) * DH + d];
    }
    __syncthreads();

    // bias lookup table: pb[r][t] = sum_d Qs[r][d] * rel_table[t][d]
    for (int idx = tid; idx < 64 * NREL; idx += 256) {
        int r = idx / NREL;
        int t = idx - r * NREL;
        const float* tr = rel_table + t * DH;
        const float* qr = Qs + r * LDP;
        float sum = 0.f;
        #pragma unroll
        for (int d = 0; d < DH; d++) sum += qr[d] * __ldg(&tr[d]);
        pb[r * PBL + t] = sum;
    }

    float m_i[4], l_i[4], o[4][4];
    #pragma unroll
    for (int i = 0; i < 4; i++) {
        m_i[i] = -INFINITY; l_i[i] = 0.f;
        #pragma unroll
        for (int j = 0; j < 4; j++) o[i][j] = 0.f;
    }

    for (int kt = 0; kt < Sq / 64; kt++) {
        __syncthreads();   // prev PV done (and pb ready on first iter)
        const int k0 = kt * 64;
        for (int idx = tid; idx < 64 * 64; idx += 256) {
            int r = idx >> 6, d = idx & 63;
            Ks[r * LDP + d] = Kg[(size_t)(k0 + r) * DH + d];
            Vs[r * LDP + d] = Vg[(size_t)(k0 + r) * DH + d];
        }
        __syncthreads();

        // scores S = Q K^T   (4x4 micro-tile per thread)
        float sv[4][4] = {};
        #pragma unroll 4
        for (int d = 0; d < 64; d++) {
            float a[4], bb[4];
            #pragma unroll
            for (int i = 0; i < 4; i++) a[i]  = Qs[(ty * 4 + i) * LDP + d];
            #pragma unroll
            for (int j = 0; j < 4; j++) bb[j] = Ks[(tx * 4 + j) * LDP + d];
            #pragma unroll
            for (int i = 0; i < 4; i++)
                #pragma unroll
                for (int j = 0; j < 4; j++)
                    sv[i][j] += a[i] * bb[j];
        }

        // bias + scale + mask, local row max
        float mloc[4];
        #pragma unroll
        for (int i = 0; i < 4; i++) {
            const int qg = q0 + ty * 4 + i;
            float mx = -INFINITY;
            #pragma unroll
            for (int j = 0; j < 4; j++) {
                const int kg = k0 + tx * 4 + j;
                int dd = kg - qg;
                dd = dd < -64 ? -64 : (dd > 64 ? 64 : dd);
                float sc = (sv[i][j] + pb[(ty * 4 + i) * PBL + dd + 64]) * 0.125f
                           + maskb[kg];
                sv[i][j] = sc;
                mx = fmaxf(mx, sc);
            }
            mloc[i] = mx;
        }

        // reduce row max across the 16 threads sharing each row
        #pragma unroll
        for (int i = 0; i < 4; i++) {
            #pragma unroll
            for (int off = 8; off; off >>= 1)
                mloc[i] = fmaxf(mloc[i], __shfl_xor_sync(0xffffffffu, mloc[i], off, 16));
        }

        // online softmax update
        #pragma unroll
        for (int i = 0; i < 4; i++) {
            const float mnew  = fmaxf(m_i[i], mloc[i]);
            const float alpha = __expf(m_i[i] - mnew);   // exp(-inf)=0 first tile
            float rs = 0.f;
            #pragma unroll
            for (int j = 0; j < 4; j++) {
                float p = __expf(sv[i][j] - mnew);
                sv[i][j] = p;
                rs += p;
            }
            #pragma unroll
            for (int off = 8; off; off >>= 1)
                rs += __shfl_xor_sync(0xffffffffu, rs, off, 16);
            l_i[i] = l_i[i] * alpha + rs;
            m_i[i] = mnew;
            #pragma unroll
            for (int j = 0; j < 4; j++) o[i][j] *= alpha;
        }

        // stage P to shared
        #pragma unroll
        for (int i = 0; i < 4; i++)
            #pragma unroll
            for (int j = 0; j < 4; j++)
                Ps[(ty * 4 + i) * LDP + tx * 4 + j] = sv[i][j];
        __syncthreads();

        // O += P V  (4 q-rows x 4 d-cols per thread)
        #pragma unroll 4
        for (int k = 0; k < 64; k++) {
            float a[4], bb[4];
            #pragma unroll
            for (int i = 0; i < 4; i++) a[i]  = Ps[(ty * 4 + i) * LDP + k];
            #pragma unroll
            for (int j = 0; j < 4; j++) bb[j] = Vs[k * LDP + tx * 4 + j];
            #pragma unroll
            for (int i = 0; i < 4; i++)
                #pragma unroll
                for (int j = 0; j < 4; j++)
                    o[i][j] += a[i] * bb[j];
        }
    }

    // epilogue: normalize and write [B,S,D]
    #pragma unroll
    for (int i = 0; i < 4; i++) {
        const int qg = q0 + ty * 4 + i;
        const float inv = 1.f / l_i[i];
        #pragma unroll
        for (int j = 0; j < 4; j++) {
            const int dc = tx * 4 + j;
            out[((size_t)(b * Sq + qg)) * Dm + h * DH + dc] = o[i][j] * inv;
        }
    }
}

// ---------------------------------------------------------------------------
// Launch
// ---------------------------------------------------------------------------
extern "C" void kernel_launch(void* const* d_in, const int* in_sizes, int n_in,
                              void* d_out, int out_size)
{
    const float* query = (const float*)d_in[0];
    const float* key   = (const float*)d_in[1];
    const float* value = (const float*)d_in[2];
    const float* mask  = (const float*)d_in[3];
    const float* Wq    = (const float*)d_in[4];
    const float* bq    = (const float*)d_in[5];
    const float* Wk    = (const float*)d_in[6];
    const float* bk    = (const float*)d_in[7];
    const float* Wv    = (const float*)d_in[8];
    const float* bv    = (const float*)d_in[9];
    const float* rel   = (const float*)d_in[10];
    float* out = (float*)d_out;

    (void)in_sizes; (void)n_in; (void)out_size;

    // 4*64*65 + 64*132 floats = 100352 bytes of dynamic smem
    const int ATTN_SMEM = (4 * 64 * LDP + 64 * PBL) * (int)sizeof(float);
    cudaFuncSetAttribute(attn_kernel,
                         cudaFuncAttributeMaxDynamicSharedMemorySize, ATTN_SMEM);

    dim3 gemm_grid(Dm / 64, (Bz * Sq) / 64, 3);
    qkv_proj_kernel<<<gemm_grid, 256>>>(query, key, value, Wq, Wk, Wv, bq, bk, bv);

    dim3 attn_grid(Sq / 64, Bz * Hn);
    attn_kernel<<<attn_grid, 256, ATTN_SMEM>>>(mask, rel, out);
}